// round 16
// baseline (speedup 1.0000x reference)
#include <cuda_runtime.h>

#define N0_ 262144
#define N1_ 32768
#define N2_ 4096
#define EPS_ 1e-5f
typedef unsigned long long ull;

__device__ float4 g_data4[N0_];
__device__ float g_y0[N0_ * 24];
__device__ float g_y1b[N1_ * 48];      // B partial (P=1)
__device__ float g_y1[N1_ * 48];
__device__ float g_yc[9][N1_ * 48];    // C partials
__device__ float g_y2[N1_ * 48];
__device__ float g_yd[4][N2_ * 96];    // D partials
__device__ float g_y3[N2_ * 96];
__device__ float g_ye[27][N2_ * 96];   // E partials
__device__ float g_y4[N2_ * 96];
__device__ float g_psum[1024 * 96];
__device__ float g_psq [1024 * 96];
__device__ float g_scale[5 * 96];
__device__ float g_shift[5 * 96];
__device__ int   g_ctrs[8];

__device__ __forceinline__ ull fmaf2(ull a, ull b, ull c) {
    ull d;
    asm("fma.rn.f32x2 %0, %1, %2, %3;" : "=l"(d) : "l"(a), "l"(b), "l"(c));
    return d;
}
__device__ __forceinline__ ull dup2(float x) {
    ull d;
    asm("mov.b64 %0, {%1, %1};" : "=l"(d) : "f"(x));
    return d;
}
__device__ __forceinline__ float2 unp2(ull v) {
    float2 r;
    asm("mov.b64 {%0, %1}, %2;" : "=f"(r.x), "=f"(r.y) : "l"(v));
    return r;
}
__device__ __forceinline__ void cpa16(void* dst_smem, const void* src) {
    unsigned d = (unsigned)__cvta_generic_to_shared(dst_smem);
    asm volatile("cp.async.cg.shared.global [%0], [%1], 16;\n"
                 :: "r"(d), "l"(src));
}
__device__ __forceinline__ void cpa_commit() {
    asm volatile("cp.async.commit_group;\n");
}
__device__ __forceinline__ void cpa_wait_all() {
    asm volatile("cp.async.wait_group 0;\n");
}

// ---------------------------------------------------------------------------
// Single-burst gather-GEMM: the block's ENTIRE weight slice [K][CIN][COUT]
// and ENTIRE gathered activation set [warp][K][8 rows][CIN] are issued as one
// cp.async burst; one wait; then pure SMEM FFMA2 compute. No loop barriers.
// Warp = 8 rows x COUT cols; lane = (row = lane>>2, colgroup = lane&3);
// CHUNKS = COUT/16 column chunks per lane; f32x2 pairs adjacent columns.
// k-split via blockIdx.z (K taps of KSTR).
// ---------------------------------------------------------------------------
template<int K, int KSTR, int CIN, int COUT, int NTH>
__global__ void __launch_bounds__(NTH)
conv_up(const float* __restrict__ xin, const int* __restrict__ neigh,
        const float* __restrict__ W, float* __restrict__ yout)
{
    constexpr int NWARP  = NTH / 32;
    constexpr int MTILE  = NWARP * 8;
    constexpr int CQ     = CIN / 4;
    constexpr int CHUNKS = COUT / 16;
    constexpr int WTOT4  = K * CIN * COUT / 4;   // 16B chunks of W slice
    constexpr int XW     = 8 * CQ;               // 16B chunks per warp per tap

    extern __shared__ float dsm[];
    float* sW = dsm;                              // [K*CIN*COUT]
    float* sX = dsm + K * CIN * COUT;             // [NWARP][K][8][CIN]

    const int tid  = threadIdx.x;
    const int w    = tid >> 5;
    const int lane = tid & 31;
    const int r    = lane >> 2;
    const int cg   = lane & 3;
    const int rowbase = blockIdx.x * MTILE;
    const int kofs    = blockIdx.z * K;
    float* __restrict__ youtz =
        yout + (long)blockIdx.z * ((long)gridDim.x * MTILE) * COUT;

    // Burst 1: whole W slice (contiguous)
    const float* Wsl = W + (long)kofs * CIN * COUT;
    for (int i = tid; i < WTOT4; i += NTH)
        cpa16(sW + i * 4, Wsl + i * 4);

    // Burst 2: all gathers for this warp's 8 rows x K taps
    float* sXw = sX + w * (K * 8 * CIN);
#pragma unroll
    for (int k = 0; k < K; k++) {
        for (int i = lane; i < XW; i += 32) {
            const int rr = i / CQ, q = i % CQ;
            const int idx = __ldg(
                &neigh[(long)(rowbase + w * 8 + rr) * KSTR + kofs + k]);
            cpa16(sXw + (k * 8 + rr) * CIN + q * 4,
                  xin + (long)idx * CIN + q * 4);
        }
    }
    cpa_commit();
    cpa_wait_all();
    __syncthreads();

    ull acc[CHUNKS][2];
#pragma unroll
    for (int ch = 0; ch < CHUNKS; ch++) { acc[ch][0] = 0ull; acc[ch][1] = 0ull; }

    for (int k = 0; k < K; k++) {
        const float* xk = sXw + (k * 8 + r) * CIN;
#pragma unroll 4
        for (int c4 = 0; c4 < CQ; c4++) {
            const float4 x4 = *reinterpret_cast<const float4*>(xk + c4 * 4);
            const float xs[4] = {x4.x, x4.y, x4.z, x4.w};
#pragma unroll
            for (int u = 0; u < 4; u++) {
                const ull xd = dup2(xs[u]);
                const float* wrow = sW + ((k * CIN) + (c4 * 4 + u)) * COUT;
#pragma unroll
                for (int ch = 0; ch < CHUNKS; ch++) {
                    ulonglong2 w2 = *reinterpret_cast<const ulonglong2*>(
                        wrow + ch * 16 + cg * 4);
                    acc[ch][0] = fmaf2(xd, w2.x, acc[ch][0]);
                    acc[ch][1] = fmaf2(xd, w2.y, acc[ch][1]);
                }
            }
        }
    }

    const long row = rowbase + w * 8 + r;
#pragma unroll
    for (int ch = 0; ch < CHUNKS; ch++) {
        float2 u0 = unp2(acc[ch][0]), u1 = unp2(acc[ch][1]);
        *reinterpret_cast<float4*>(&youtz[row * COUT + ch * 16 + cg * 4]) =
            make_float4(u0.x, u0.y, u1.x, u1.y);
    }
}

// Combine P k-split partials -> y + BN stats + last-block finalize.
template<int COUT, int P, int R>
__global__ void __launch_bounds__(COUT)
combine_bn(const float* __restrict__ parts, long pstride, float* __restrict__ y,
           float* __restrict__ psum, float* __restrict__ psq,
           const float* __restrict__ gamma, const float* __restrict__ beta,
           float* __restrict__ oscale, float* __restrict__ oshift,
           float invM, int* __restrict__ ctr)
{
    __shared__ int sLast;
    const int c = threadIdx.x;
    const int rbase = blockIdx.x * R;
    float s = 0.f, q = 0.f;
    for (int r = rbase; r < rbase + R; r++) {
        const long i = (long)r * COUT + c;
        float v = 0.f;
#pragma unroll
        for (int p = 0; p < P; p++) v += parts[p * pstride + i];
        y[i] = v;
        s += v; q += v * v;
    }
    psum[(long)blockIdx.x * COUT + c] = s;
    psq [(long)blockIdx.x * COUT + c] = q;
    __threadfence();
    __syncthreads();
    if (c == 0) {
        int old = atomicAdd(ctr, 1);
        sLast = (old == (int)gridDim.x - 1);
    }
    __syncthreads();
    if (sLast) {
        __threadfence();
        float ss = 0.f, qq = 0.f;
        for (int b = 0; b < (int)gridDim.x; b++) {
            ss += psum[(long)b * COUT + c];
            qq += psq [(long)b * COUT + c];
        }
        const float mean = ss * invM;
        const float var  = qq * invM - mean * mean;
        const float sc   = gamma[c] * rsqrtf(var + EPS_);
        oscale[c] = sc;
        oshift[c] = beta[c] - mean * sc;
        __syncthreads();
        if (c == 0) *ctr = 0;
    }
}

// BN+ReLU in place (vectorized).
template<int COUT>
__global__ void __launch_bounds__(256)
norm_relu(float4* __restrict__ y, const float* __restrict__ scale,
          const float* __restrict__ shift, int n4)
{
    const int i = blockIdx.x * 256 + threadIdx.x;
    if (i < n4) {
        const int c = (i % (COUT / 4)) * 4;
        float4 v = y[i];
        v.x = fmaxf(fmaf(v.x, __ldg(scale+c+0), __ldg(shift+c+0)), 0.f);
        v.y = fmaxf(fmaf(v.y, __ldg(scale+c+1), __ldg(shift+c+1)), 0.f);
        v.z = fmaxf(fmaf(v.z, __ldg(scale+c+2), __ldg(shift+c+2)), 0.f);
        v.w = fmaxf(fmaf(v.w, __ldg(scale+c+3), __ldg(shift+c+3)), 0.f);
        y[i] = v;
    }
}

// Stage A: padded float4 rows, one thread per row, f32x2 channel pairs.
__global__ void __launch_bounds__(256)
conv_stageA(const float4* __restrict__ x4, const int* __restrict__ neigh,
            const float* __restrict__ W, float* __restrict__ yout,
            float* __restrict__ psum, float* __restrict__ psq,
            const float* __restrict__ gamma, const float* __restrict__ beta,
            float* __restrict__ oscale, float* __restrict__ oshift,
            float invM, int* __restrict__ ctr)
{
    __shared__ float sW[27 * 3 * 24];
    __shared__ int   sIdx[256 * 27];
    __shared__ float sRed[8][24][2];
    __shared__ int   sLast;

    const int tid = threadIdx.x;
    const int row = blockIdx.x * 256 + tid;

    for (int i = tid; i < 27 * 3 * 24; i += 256) sW[i] = W[i];
    const long nbase = (long)blockIdx.x * 256 * 27;
    for (int i = tid; i < 256 * 27; i += 256) sIdx[i] = neigh[nbase + i];
    __syncthreads();

    ull a2[12];
#pragma unroll
    for (int j = 0; j < 12; j++) a2[j] = 0ull;

#pragma unroll 3
    for (int k = 0; k < 27; k++) {
        float4 xv = x4[sIdx[tid * 27 + k]];
        const float v[3] = {xv.x, xv.y, xv.z};
#pragma unroll
        for (int c = 0; c < 3; c++) {
            const ull xd = dup2(v[c]);
            const ulonglong2* wr =
                reinterpret_cast<const ulonglong2*>(&sW[(k * 3 + c) * 24]);
#pragma unroll
            for (int t = 0; t < 6; t++) {
                ulonglong2 wp = wr[t];
                a2[2*t+0] = fmaf2(xd, wp.x, a2[2*t+0]);
                a2[2*t+1] = fmaf2(xd, wp.y, a2[2*t+1]);
            }
        }
    }

    float acc[24];
#pragma unroll
    for (int j = 0; j < 12; j++) {
        float2 u = unp2(a2[j]);
        acc[2*j] = u.x; acc[2*j+1] = u.y;
    }
#pragma unroll
    for (int j = 0; j < 24; j += 4)
        *reinterpret_cast<float4*>(&yout[(long)row * 24 + j]) =
            make_float4(acc[j], acc[j+1], acc[j+2], acc[j+3]);

    const int lane = tid & 31, warp = tid >> 5;
#pragma unroll
    for (int j = 0; j < 24; j++) {
        float s = acc[j], q = acc[j] * acc[j];
#pragma unroll
        for (int off = 16; off > 0; off >>= 1) {
            s += __shfl_down_sync(0xFFFFFFFFu, s, off);
            q += __shfl_down_sync(0xFFFFFFFFu, q, off);
        }
        if (lane == 0) { sRed[warp][j][0] = s; sRed[warp][j][1] = q; }
    }
    __syncthreads();
    if (tid < 24) {
        float s = 0.f, q = 0.f;
#pragma unroll
        for (int w = 0; w < 8; w++) { s += sRed[w][tid][0]; q += sRed[w][tid][1]; }
        psum[(long)blockIdx.x * 24 + tid] = s;
        psq [(long)blockIdx.x * 24 + tid] = q;
    }
    __threadfence();
    __syncthreads();
    if (tid == 0) {
        int old = atomicAdd(ctr, 1);
        sLast = (old == (int)gridDim.x - 1);
    }
    __syncthreads();
    if (sLast) {
        __threadfence();
        for (int d = warp; d < 24; d += 8) {
            float s = 0.f, q = 0.f;
            for (int b = lane; b < (int)gridDim.x; b += 32) {
                s += psum[(long)b * 24 + d];
                q += psq [(long)b * 24 + d];
            }
#pragma unroll
            for (int off = 16; off > 0; off >>= 1) {
                s += __shfl_down_sync(0xFFFFFFFFu, s, off);
                q += __shfl_down_sync(0xFFFFFFFFu, q, off);
            }
            if (lane == 0) {
                const float mean = s * invM;
                const float var  = q * invM - mean * mean;
                const float sc   = gamma[d] * rsqrtf(var + EPS_);
                oscale[d] = sc;
                oshift[d] = beta[d] - mean * sc;
            }
        }
        __syncthreads();
        if (tid == 0) *ctr = 0;
    }
}

__global__ void pad4_kernel(const float* __restrict__ d, float4* __restrict__ o)
{
    const int i = blockIdx.x * 256 + threadIdx.x;
    if (i < N0_)
        o[i] = make_float4(d[3*i], d[3*i+1], d[3*i+2], 0.f);
}

__global__ void final_norm(const float* __restrict__ y,
                           const float* __restrict__ scale,
                           const float* __restrict__ shift,
                           float* __restrict__ out, int total, int cout)
{
    const int i = blockIdx.x * 256 + threadIdx.x;
    if (i < total) {
        const int d = i % cout;
        out[i] = fmaxf(fmaf(y[i], scale[d], shift[d]), 0.f);
    }
}

extern "C" void kernel_launch(void* const* d_in, const int* in_sizes, int n_in,
                              void* d_out, int out_size)
{
    const float* data   = (const float*)d_in[0];
    const int*   neigh0 = (const int*)  d_in[1];
    const int*   child0 = (const int*)  d_in[2];
    const int*   neigh1 = (const int*)  d_in[3];
    const int*   child1 = (const int*)  d_in[4];
    const int*   neigh2 = (const int*)  d_in[5];
    const float* w0  = (const float*)d_in[6];
    const float* g0  = (const float*)d_in[7];
    const float* b0  = (const float*)d_in[8];
    const float* wd0 = (const float*)d_in[9];
    const float* gd0 = (const float*)d_in[10];
    const float* bd0 = (const float*)d_in[11];
    const float* w1  = (const float*)d_in[12];
    const float* g1  = (const float*)d_in[13];
    const float* b1  = (const float*)d_in[14];
    const float* wd1 = (const float*)d_in[15];
    const float* gd1 = (const float*)d_in[16];
    const float* bd1 = (const float*)d_in[17];
    const float* wp  = (const float*)d_in[18];
    const float* gp  = (const float*)d_in[19];
    const float* bp  = (const float*)d_in[20];

    float4 *x4;
    float *y0,*y1b,*y1,*yc,*y2,*yd,*y3,*ye,*y4,*psum,*psq,*scl,*shf; int *ctrs;
    cudaGetSymbolAddress((void**)&x4,   g_data4);
    cudaGetSymbolAddress((void**)&y0,   g_y0);
    cudaGetSymbolAddress((void**)&y1b,  g_y1b);
    cudaGetSymbolAddress((void**)&y1,   g_y1);
    cudaGetSymbolAddress((void**)&yc,   g_yc);
    cudaGetSymbolAddress((void**)&y2,   g_y2);
    cudaGetSymbolAddress((void**)&yd,   g_yd);
    cudaGetSymbolAddress((void**)&y3,   g_y3);
    cudaGetSymbolAddress((void**)&ye,   g_ye);
    cudaGetSymbolAddress((void**)&y4,   g_y4);
    cudaGetSymbolAddress((void**)&psum, g_psum);
    cudaGetSymbolAddress((void**)&psq,  g_psq);
    cudaGetSymbolAddress((void**)&scl,  g_scale);
    cudaGetSymbolAddress((void**)&shf,  g_shift);
    cudaGetSymbolAddress((void**)&ctrs, g_ctrs);

    // Single-burst conv kernels (W slice fully SMEM-resident per block)
    auto kB = conv_up<8, 8, 24, 48, 128>;    // MTILE 32
    auto kC = conv_up<3, 27, 48, 48, 128>;   // k-split x9
    auto kD = conv_up<2, 8, 48, 96, 128>;    // k-split x4
    auto kE = conv_up<1, 27, 96, 96, 128>;   // k-split x27
    const int smB = (8*24*48 + 4*8*8*24) * 4;   // 61440
    const int smC = (3*48*48 + 4*3*8*48) * 4;   // 46080
    const int smD = (2*48*96 + 4*2*8*48) * 4;   // 49152
    const int smE = (1*96*96 + 4*1*8*96) * 4;   // 49152
    cudaFuncSetAttribute(kB, cudaFuncAttributeMaxDynamicSharedMemorySize, smB);
    cudaFuncSetAttribute(kC, cudaFuncAttributeMaxDynamicSharedMemorySize, smC);
    cudaFuncSetAttribute(kD, cudaFuncAttributeMaxDynamicSharedMemorySize, smD);
    cudaFuncSetAttribute(kE, cudaFuncAttributeMaxDynamicSharedMemorySize, smE);

    // 0: pad input rows to float4
    pad4_kernel<<<(N0_ + 255) / 256, 256>>>(data, x4);

    // 1: Stage A -> y0 raw + BN0
    conv_stageA<<<N0_/256, 256>>>(x4, neigh0, w0, y0, psum, psq,
                                  g0, b0, scl, shf, 1.f / N0_, ctrs + 0);
    // 2: normalize y0
    norm_relu<24><<<(N0_*24/4 + 255)/256, 256>>>(
        (float4*)y0, scl, shf, N0_*24/4);

    // 3: Stage B conv -> y1b
    kB<<<dim3(N1_/32, 1, 1), 128, smB>>>(y0, child0, wd0, y1b);
    // 4: copy + BN1 stats/finalize
    combine_bn<48, 1, 64><<<N1_/64, 48>>>(
        y1b, 0, y1, psum, psq,
        gd0, bd0, scl + 96, shf + 96, 1.f / N1_, ctrs + 1);
    // 5: normalize y1
    norm_relu<48><<<(N1_*48/4 + 255)/256, 256>>>(
        (float4*)y1, scl + 96, shf + 96, N1_*48/4);

    // 6: Stage C conv, k-split x9 -> yc partials
    kC<<<dim3(N1_/32, 1, 9), 128, smC>>>(y1, neigh1, w1, yc);
    // 7: combine -> y2 + BN2
    combine_bn<48, 9, 64><<<N1_/64, 48>>>(
        yc, (long)N1_ * 48, y2, psum, psq,
        g1, b1, scl + 192, shf + 192, 1.f / N1_, ctrs + 2);
    // 8: normalize y2
    norm_relu<48><<<(N1_*48/4 + 255)/256, 256>>>(
        (float4*)y2, scl + 192, shf + 192, N1_*48/4);

    // 9: Stage D conv, k-split x4 -> yd partials
    kD<<<dim3(N2_/32, 1, 4), 128, smD>>>(y2, child1, wd1, yd);
    // 10: combine -> y3 + BN3
    combine_bn<96, 4, 64><<<N2_/64, 96>>>(
        yd, (long)N2_ * 96, y3, psum, psq,
        gd1, bd1, scl + 288, shf + 288, 1.f / N2_, ctrs + 3);
    // 11: normalize y3
    norm_relu<96><<<(N2_*96/4 + 255)/256, 256>>>(
        (float4*)y3, scl + 288, shf + 288, N2_*96/4);

    // 12: Stage E conv, k-split x27 -> ye partials
    kE<<<dim3(N2_/32, 1, 27), 128, smE>>>(y3, neigh2, wp, ye);
    // 13: combine -> y4 + BN4
    combine_bn<96, 27, 64><<<N2_/64, 96>>>(
        ye, (long)N2_ * 96, y4, psum, psq,
        gp, bp, scl + 384, shf + 384, 1.f / N2_, ctrs + 5);

    // 14: final BN + ReLU -> d_out
    final_norm<<<(N2_ * 96 + 255) / 256, 256>>>(
        y4, scl + 384, shf + 384, (float*)d_out, N2_ * 96, 96);
}